// round 14
// baseline (speedup 1.0000x reference)
#include <cuda_runtime.h>
#include <cstdint>

#define NN 8192
#define KF 256
#define CT 32
#define EPSF 1e-10f

// ---------------- scratch ----------------
__device__ float g_AcT[(size_t)KF * NN];   // transposed masked a*cos, 8 MB
__device__ float g_AsT[(size_t)KF * NN];   // transposed masked a*sin, 8 MB
__device__ int   g_kk[(size_t)NN * CT];    // CSR k indices (ascending)
__device__ float g_cv[(size_t)NN * CT];    // CSR c values
__device__ float g_sv[(size_t)NN * CT];    // CSR s values
__device__ float g_sqf[NN];                // f32 sq (ref-order emulated)
__device__ float g_den[NN];                // f32 rowsum + eps (ref-order emulated)
__device__ double g_psum;
__device__ unsigned long long g_pcnt;
__device__ float g_tau;

__global__ void zero_stats_kernel() { g_psum = 0.0; g_pcnt = 0ull; }

// ---------------- build: top-32, fp32 trig, transposed dense + CSR, sq ---------
__global__ void build_kernel(const float* __restrict__ P, const float* __restrict__ A) {
    const int row = blockIdx.x, t = threadIdx.x;
    __shared__ unsigned long long keys[KF];
    __shared__ float a2s[KF];
    __shared__ int flg[KF];

    const float a = A[(size_t)row * KF + t];
    const float p = P[(size_t)row * KF + t];
    unsigned long long key =
        ((unsigned long long)__float_as_uint(a) << 32) | (unsigned)(0xFFFFFFFFu - t);
    keys[t] = key;
    __syncthreads();
    int rank = 0;
#pragma unroll 8
    for (int i = 0; i < KF; i++) rank += (keys[i] > key);
    const bool sel = rank < CT;

    float c = 0.f, s = 0.f;
    if (sel) { c = __fmul_rn(a, cosf(p)); s = __fmul_rn(a, sinf(p)); }
    g_AcT[(size_t)t * NN + row] = c;
    g_AsT[(size_t)t * NN + row] = s;

    a2s[t] = sel ? __fmul_rn(a, a) : 0.f;
    flg[t] = sel ? 1 : 0;
    __syncthreads();
    if (t < 32) {   // emulate f32 warp row-reduce: strided serial 8 + shfl tree
        float acc = 0.f;
#pragma unroll
        for (int i = 0; i < 8; i++) acc = __fadd_rn(acc, a2s[t + 32 * i]);
#pragma unroll
        for (int d = 16; d; d >>= 1)
            acc = __fadd_rn(acc, __shfl_down_sync(0xffffffffu, acc, d));
        if (t == 0) g_sqf[row] = acc;
    }
    if (sel) {
        int pos = 0;
        for (int i = 0; i < t; i++) pos += flg[i];
        g_kk[(size_t)row * CT + pos] = t;
        g_cv[(size_t)row * CT + pos] = c;
        g_sv[(size_t)row * CT + pos] = s;
    }
}

// ---------------- entry kernel: bit-exact serial-k fp32 R entries --------------
// Block = 128 n x 64 m. Dense f32 tile of Ac/As^T columns in smem; CSR of the
// 128 n-rows in smem. Per entry: 32 serial FMAs (ascending k) per c and s
// accumulator == bitwise cuBLAS-style dense serial-k (masked terms are exact
// +/-0 no-ops). Upper-triangle blocks only (R is bitwise symmetric).
#define SM_TC   0
#define SM_TS   (256 * 32 * 8)
#define SM_KK   (2 * 256 * 32 * 8)
#define SM_CC   (SM_KK + 128 * 32 * 4)
#define SM_SS   (SM_CC + 128 * 32 * 4)
#define SM_TOT  (SM_SS + 128 * 32 * 4)      // 180224 B

__global__ void __launch_bounds__(256) entry_kernel(float* __restrict__ out) {
    const int mBase = blockIdx.x * 64, nBase = blockIdx.y * 128;
    if (mBase + 64 <= nBase) return;        // keep blocks touching m >= n
    extern __shared__ char smem[];
    float2* tc = (float2*)(smem + SM_TC);   // [k][32 float2]
    float2* ts = (float2*)(smem + SM_TS);
    int*   kk = (int*)(smem + SM_KK);       // [128][32]
    float* cc = (float*)(smem + SM_CC);
    float* ss = (float*)(smem + SM_SS);

    const int t = threadIdx.x;
    for (int idx = t; idx < 256 * 32; idx += 256) {
        const int k = idx >> 5, pr = idx & 31;
        tc[idx] = *(const float2*)(g_AcT + (size_t)k * NN + mBase + 2 * pr);
        ts[idx] = *(const float2*)(g_AsT + (size_t)k * NN + mBase + 2 * pr);
    }
    for (int idx = t; idx < 128 * 32; idx += 256) {
        kk[idx] = g_kk[(size_t)nBase * CT + idx];
        cc[idx] = g_cv[(size_t)nBase * CT + idx];
        ss[idx] = g_sv[(size_t)nBase * CT + idx];
    }
    __syncthreads();

    const int w = t >> 5, lane = t & 31;
    const float2 sqm = *(const float2*)(g_sqf + mBase + 2 * lane);

#pragma unroll 1
    for (int jj = 0; jj < 16; jj++) {
        const int nl = w * 16 + jj;
        const int n = nBase + nl;
        const float sqn = g_sqf[n];
        float2 ac = make_float2(0.f, 0.f), as2 = make_float2(0.f, 0.f);
#pragma unroll
        for (int j = 0; j < 32; j++) {
            const int k = kk[nl * 32 + j];
            const float c = cc[nl * 32 + j], s = ss[nl * 32 + j];
            const float2 x = tc[k * 32 + lane];
            const float2 y = ts[k * 32 + lane];
            ac.x = __fmaf_rn(c, x.x, ac.x);  ac.y = __fmaf_rn(c, x.y, ac.y);
            as2.x = __fmaf_rn(s, y.x, as2.x); as2.y = __fmaf_rn(s, y.y, as2.y);
        }
        float2 r;
        r.x = __fdiv_rn(__fadd_rn(ac.x, as2.x),
                        __fsqrt_rn(__fadd_rn(__fmul_rn(sqn, sqm.x), EPSF)));
        r.y = __fdiv_rn(__fadd_rn(ac.y, as2.y),
                        __fsqrt_rn(__fadd_rn(__fmul_rn(sqn, sqm.y), EPSF)));
        *(float2*)(out + (size_t)n * NN + mBase + 2 * lane) = r;
    }
}

// ---------------- mirror: strictly-lower 32-tiles from upper (bitwise equal) ---
__global__ void mirror_kernel(float* __restrict__ R) {
    const int bx = blockIdx.x, by = blockIdx.y;
    if (bx >= by) return;
    __shared__ float tile[32][33];
    const int x = threadIdx.x;
    for (int r = threadIdx.y; r < 32; r += 8)
        tile[r][x] = R[(size_t)(bx * 32 + r) * NN + by * 32 + x];
    __syncthreads();
    for (int r = threadIdx.y; r < 32; r += 8)
        R[(size_t)(by * 32 + r) * NN + bx * 32 + x] = tile[x][r];
}

// ---------------- rowsum: emulate XLA:GPU f32 row-reduce order ------------------
// 1024 threads, float2 strided loads (i ascending), serial .x/.y adds, warp
// shfl-down tree, 32 partials, warp0 shfl-down tree. den = fl32(sum + 1e-10f).
__global__ void __launch_bounds__(1024) rowsum_kernel(const float* __restrict__ R) {
    const int n = blockIdx.x, t = threadIdx.x;
    const float2* r2 = (const float2*)(R + (size_t)n * NN);
    __shared__ float sp[32];
    float acc = 0.f;
#pragma unroll
    for (int i = 0; i < 4; i++) {
        const float2 v = r2[t + 1024 * i];
        acc = __fadd_rn(acc, v.x);
        acc = __fadd_rn(acc, v.y);
    }
#pragma unroll
    for (int d = 16; d; d >>= 1)
        acc = __fadd_rn(acc, __shfl_down_sync(0xffffffffu, acc, d));
    if ((t & 31) == 0) sp[t >> 5] = acc;
    __syncthreads();
    if (t < 32) {
        float a = sp[t];
#pragma unroll
        for (int d = 16; d; d >>= 1)
            a = __fadd_rn(a, __shfl_down_sync(0xffffffffu, a, d));
        if (t == 0) g_den[n] = __fadd_rn(a, EPSF);
    }
}

// ---------------- stats: global positive mean inputs (fp64, deterministic) -----
__global__ void stats_kernel(const float* __restrict__ R) {
    const int row = blockIdx.x, t = threadIdx.x;
    const float* r = R + (size_t)row * NN;
    const float den = g_den[row];
    __shared__ double ds[256];
    __shared__ unsigned int cs[256];
    double ps = 0.0; unsigned int pc = 0;
#pragma unroll
    for (int j = 0; j < 32; j++) {
        const float rp = __fdiv_rn(r[t + 256 * j], den);
        if (rp > 0.f) { ps += (double)rp; pc++; }
    }
    ds[t] = ps; cs[t] = pc;
    __syncthreads();
    for (int o = 128; o; o >>= 1) {
        if (t < o) { ds[t] += ds[t + o]; cs[t] += cs[t + o]; }
        __syncthreads();
    }
    if (t == 0) {
        atomicAdd(&g_psum, ds[0]);
        atomicAdd(&g_pcnt, (unsigned long long)cs[0]);
    }
}

__global__ void tau_kernel() {
    double cnt = (double)g_pcnt;
    if (cnt < 1.0) cnt = 1.0;
    const double mp = g_psum / cnt;
    g_tau = (mp > 0.0) ? (float)mp : 1.0f;
}

// ---------------- threshold: R_hat = where(R' >= tau, R', 0) -------------------
__global__ void thresh_kernel(float* __restrict__ R) {
    const int i = blockIdx.x * blockDim.x + threadIdx.x;  // float4 index
    float4* R4 = (float4*)R;
    float4 v = R4[i];
    const float den = g_den[i >> 11];
    const float tau = g_tau;
    float x;
    x = __fdiv_rn(v.x, den); v.x = (x >= tau) ? x : 0.f;
    x = __fdiv_rn(v.y, den); v.y = (x >= tau) ? x : 0.f;
    x = __fdiv_rn(v.z, den); v.z = (x >= tau) ? x : 0.f;
    x = __fdiv_rn(v.w, den); v.w = (x >= tau) ? x : 0.f;
    R4[i] = v;
}

// ---------------- launch ----------------
extern "C" void kernel_launch(void* const* d_in, const int* in_sizes, int n_in,
                              void* d_out, int out_size) {
    const float* P = (const float*)d_in[0];
    const float* A = (const float*)d_in[1];
    float* out = (float*)d_out;

    cudaFuncSetAttribute(entry_kernel,
                         cudaFuncAttributeMaxDynamicSharedMemorySize, SM_TOT);

    zero_stats_kernel<<<1, 1>>>();
    build_kernel<<<NN, 256>>>(P, A);
    entry_kernel<<<dim3(NN / 64, NN / 128), 256, SM_TOT>>>(out);
    mirror_kernel<<<dim3(NN / 32, NN / 32), dim3(32, 8)>>>(out);
    rowsum_kernel<<<NN, 1024>>>(out);
    stats_kernel<<<NN, 256>>>(out);
    tau_kernel<<<1, 1>>>();
    thresh_kernel<<<(NN / 4) * (NN / 256), 256>>>(out);
}

// round 16
// speedup vs baseline: 1.0003x; 1.0003x over previous
#include <cuda_runtime.h>
#include <cstdint>

#define NN 8192
#define KF 256
#define CT 32
#define EPSF 1e-10f

// ---------------- scratch ----------------
__device__ float g_AcT[(size_t)KF * NN];   // transposed masked a*cos, 8 MB
__device__ float g_AsT[(size_t)KF * NN];   // transposed masked a*sin, 8 MB
__device__ int   g_kk[(size_t)NN * CT];    // CSR k indices (ascending)
__device__ float g_cv[(size_t)NN * CT];    // CSR c values
__device__ float g_sv[(size_t)NN * CT];    // CSR s values
__device__ float g_sqf[NN];                // f32 sq (ref-order emulated)
__device__ float g_den[NN];                // f32 rowsum + eps (ref-order emulated)
__device__ float g_rcp[NN];                // fl32(1/den), for Markstein division
__device__ double g_psum;
__device__ unsigned long long g_pcnt;
__device__ float g_tau;

__global__ void zero_stats_kernel() { g_psum = 0.0; g_pcnt = 0ull; }

// Markstein correctly-rounded-division emulation: with y = fl(1/den) and FMA,
// q = fl(fma(fl(v - fl(v*y)*den), y, fl(v*y))) equals __fdiv_rn(v, den) except
// with probability ~2^-24 (1-ulp boundary cases) — applied consistently in
// stats and thresh so internal consistency is preserved.
__device__ __forceinline__ float mdiv(float v, float den, float y) {
    const float q0 = __fmul_rn(v, y);
    const float r  = __fmaf_rn(-q0, den, v);
    return __fmaf_rn(r, y, q0);
}

// ---------------- build: top-32, fp32 trig, transposed dense + CSR, sq ---------
__global__ void build_kernel(const float* __restrict__ P, const float* __restrict__ A) {
    const int row = blockIdx.x, t = threadIdx.x;
    __shared__ unsigned long long keys[KF];
    __shared__ float a2s[KF];
    __shared__ int flg[KF];

    const float a = A[(size_t)row * KF + t];
    const float p = P[(size_t)row * KF + t];
    unsigned long long key =
        ((unsigned long long)__float_as_uint(a) << 32) | (unsigned)(0xFFFFFFFFu - t);
    keys[t] = key;
    __syncthreads();
    int rank = 0;
#pragma unroll 8
    for (int i = 0; i < KF; i++) rank += (keys[i] > key);
    const bool sel = rank < CT;

    float c = 0.f, s = 0.f;
    if (sel) { c = __fmul_rn(a, cosf(p)); s = __fmul_rn(a, sinf(p)); }
    g_AcT[(size_t)t * NN + row] = c;
    g_AsT[(size_t)t * NN + row] = s;

    a2s[t] = sel ? __fmul_rn(a, a) : 0.f;
    flg[t] = sel ? 1 : 0;
    __syncthreads();
    if (t < 32) {   // emulate f32 warp row-reduce: strided serial 8 + shfl tree
        float acc = 0.f;
#pragma unroll
        for (int i = 0; i < 8; i++) acc = __fadd_rn(acc, a2s[t + 32 * i]);
#pragma unroll
        for (int d = 16; d; d >>= 1)
            acc = __fadd_rn(acc, __shfl_down_sync(0xffffffffu, acc, d));
        if (t == 0) g_sqf[row] = acc;
    }
    if (sel) {
        int pos = 0;
        for (int i = 0; i < t; i++) pos += flg[i];
        g_kk[(size_t)row * CT + pos] = t;
        g_cv[(size_t)row * CT + pos] = c;
        g_sv[(size_t)row * CT + pos] = s;
    }
}

// ---------------- entry kernel: bit-exact serial-k fp32 R entries --------------
// Block = 128 n x 64 m. Dense f32 tile of Ac/As^T columns in smem; CSR of the
// 128 n-rows in smem. Per entry: 32 serial FMAs (ascending k) per c and s
// accumulator == bitwise cuBLAS-style dense serial-k (masked terms are exact
// +/-0 no-ops). Upper-triangle blocks only (R is bitwise symmetric).
#define SM_TC   0
#define SM_TS   (256 * 32 * 8)
#define SM_KK   (2 * 256 * 32 * 8)
#define SM_CC   (SM_KK + 128 * 32 * 4)
#define SM_SS   (SM_CC + 128 * 32 * 4)
#define SM_TOT  (SM_SS + 128 * 32 * 4)      // 180224 B

__global__ void __launch_bounds__(256) entry_kernel(float* __restrict__ out) {
    const int mBase = blockIdx.x * 64, nBase = blockIdx.y * 128;
    if (mBase + 64 <= nBase) return;        // keep blocks touching m >= n
    extern __shared__ char smem[];
    float2* tc = (float2*)(smem + SM_TC);   // [k][32 float2]
    float2* ts = (float2*)(smem + SM_TS);
    int*   kk = (int*)(smem + SM_KK);       // [128][32]
    float* cc = (float*)(smem + SM_CC);
    float* ss = (float*)(smem + SM_SS);

    const int t = threadIdx.x;
    for (int idx = t; idx < 256 * 32; idx += 256) {
        const int k = idx >> 5, pr = idx & 31;
        tc[idx] = *(const float2*)(g_AcT + (size_t)k * NN + mBase + 2 * pr);
        ts[idx] = *(const float2*)(g_AsT + (size_t)k * NN + mBase + 2 * pr);
    }
    for (int idx = t; idx < 128 * 32; idx += 256) {
        kk[idx] = g_kk[(size_t)nBase * CT + idx];
        cc[idx] = g_cv[(size_t)nBase * CT + idx];
        ss[idx] = g_sv[(size_t)nBase * CT + idx];
    }
    __syncthreads();

    const int w = t >> 5, lane = t & 31;
    const float2 sqm = *(const float2*)(g_sqf + mBase + 2 * lane);

#pragma unroll 1
    for (int jj = 0; jj < 16; jj++) {
        const int nl = w * 16 + jj;
        const int n = nBase + nl;
        const float sqn = g_sqf[n];
        float2 ac = make_float2(0.f, 0.f), as2 = make_float2(0.f, 0.f);
#pragma unroll
        for (int j = 0; j < 32; j++) {
            const int k = kk[nl * 32 + j];
            const float c = cc[nl * 32 + j], s = ss[nl * 32 + j];
            const float2 x = tc[k * 32 + lane];
            const float2 y = ts[k * 32 + lane];
            ac.x = __fmaf_rn(c, x.x, ac.x);  ac.y = __fmaf_rn(c, x.y, ac.y);
            as2.x = __fmaf_rn(s, y.x, as2.x); as2.y = __fmaf_rn(s, y.y, as2.y);
        }
        float2 r;
        r.x = __fdiv_rn(__fadd_rn(ac.x, as2.x),
                        __fsqrt_rn(__fadd_rn(__fmul_rn(sqn, sqm.x), EPSF)));
        r.y = __fdiv_rn(__fadd_rn(ac.y, as2.y),
                        __fsqrt_rn(__fadd_rn(__fmul_rn(sqn, sqm.y), EPSF)));
        *(float2*)(out + (size_t)n * NN + mBase + 2 * lane) = r;
    }
}

// ---------------- mirror: strictly-lower 32-tiles from upper (bitwise equal) ---
__global__ void mirror_kernel(float* __restrict__ R) {
    const int bx = blockIdx.x, by = blockIdx.y;
    if (bx >= by) return;
    __shared__ float tile[32][33];
    const int x = threadIdx.x;
    for (int r = threadIdx.y; r < 32; r += 8)
        tile[r][x] = R[(size_t)(bx * 32 + r) * NN + by * 32 + x];
    __syncthreads();
    for (int r = threadIdx.y; r < 32; r += 8)
        R[(size_t)(by * 32 + r) * NN + bx * 32 + x] = tile[x][r];
}

// ---------------- fused rowsum + stats (one pass over R) -----------------------
// Rowsum reduce order is byte-identical to R14's rowsum_kernel (so g_den bits
// are unchanged). Stats then reuses the register-resident values with Markstein
// division; fp64 tau accumulation (order-insensitive at fp32 granularity).
__global__ void __launch_bounds__(1024) rowsum_stats_kernel(const float* __restrict__ R) {
    const int n = blockIdx.x, t = threadIdx.x;
    const float2* r2 = (const float2*)(R + (size_t)n * NN);
    __shared__ float sp[32];
    __shared__ float sden, srcp;
    __shared__ double dsp[32];
    __shared__ unsigned int csp[32];

    float2 v[4];
    float acc = 0.f;
#pragma unroll
    for (int i = 0; i < 4; i++) {
        v[i] = r2[t + 1024 * i];
        acc = __fadd_rn(acc, v[i].x);
        acc = __fadd_rn(acc, v[i].y);
    }
#pragma unroll
    for (int d = 16; d; d >>= 1)
        acc = __fadd_rn(acc, __shfl_down_sync(0xffffffffu, acc, d));
    if ((t & 31) == 0) sp[t >> 5] = acc;
    __syncthreads();
    if (t < 32) {
        float a = sp[t];
#pragma unroll
        for (int d = 16; d; d >>= 1)
            a = __fadd_rn(a, __shfl_down_sync(0xffffffffu, a, d));
        if (t == 0) {
            const float den = __fadd_rn(a, EPSF);
            g_den[n] = den;
            sden = den;
            const float y = __fdiv_rn(1.0f, den);
            g_rcp[n] = y;
            srcp = y;
        }
    }
    __syncthreads();

    const float den = sden, y = srcp;
    double ps = 0.0; unsigned int pc = 0;
#pragma unroll
    for (int i = 0; i < 4; i++) {
        float rp;
        rp = mdiv(v[i].x, den, y); if (rp > 0.f) { ps += (double)rp; pc++; }
        rp = mdiv(v[i].y, den, y); if (rp > 0.f) { ps += (double)rp; pc++; }
    }
#pragma unroll
    for (int d = 16; d; d >>= 1) {
        ps += __shfl_down_sync(0xffffffffu, ps, d);
        pc += __shfl_down_sync(0xffffffffu, pc, d);
    }
    if ((t & 31) == 0) { dsp[t >> 5] = ps; csp[t >> 5] = pc; }
    __syncthreads();
    if (t < 32) {
        double a = dsp[t]; unsigned int c = csp[t];
#pragma unroll
        for (int d = 16; d; d >>= 1) {
            a += __shfl_down_sync(0xffffffffu, a, d);
            c += __shfl_down_sync(0xffffffffu, c, d);
        }
        if (t == 0) {
            atomicAdd(&g_psum, a);
            atomicAdd(&g_pcnt, (unsigned long long)c);
        }
    }
}

__global__ void tau_kernel() {
    double cnt = (double)g_pcnt;
    if (cnt < 1.0) cnt = 1.0;
    const double mp = g_psum / cnt;
    g_tau = (mp > 0.0) ? (float)mp : 1.0f;
}

// ---------------- threshold: R_hat = where(R' >= tau, R', 0) -------------------
__global__ void thresh_kernel(float* __restrict__ R) {
    const int i = blockIdx.x * blockDim.x + threadIdx.x;  // float4 index
    float4* R4 = (float4*)R;
    float4 v = R4[i];
    const int row = i >> 11;                               // 2048 float4 per row
    const float den = g_den[row];
    const float y = g_rcp[row];
    const float tau = g_tau;
    float x;
    x = mdiv(v.x, den, y); v.x = (x >= tau) ? x : 0.f;
    x = mdiv(v.y, den, y); v.y = (x >= tau) ? x : 0.f;
    x = mdiv(v.z, den, y); v.z = (x >= tau) ? x : 0.f;
    x = mdiv(v.w, den, y); v.w = (x >= tau) ? x : 0.f;
    R4[i] = v;
}

// ---------------- launch ----------------
extern "C" void kernel_launch(void* const* d_in, const int* in_sizes, int n_in,
                              void* d_out, int out_size) {
    const float* P = (const float*)d_in[0];
    const float* A = (const float*)d_in[1];
    float* out = (float*)d_out;

    cudaFuncSetAttribute(entry_kernel,
                         cudaFuncAttributeMaxDynamicSharedMemorySize, SM_TOT);

    zero_stats_kernel<<<1, 1>>>();
    build_kernel<<<NN, 256>>>(P, A);
    entry_kernel<<<dim3(NN / 64, NN / 128), 256, SM_TOT>>>(out);
    mirror_kernel<<<dim3(NN / 32, NN / 32), dim3(32, 8)>>>(out);
    rowsum_stats_kernel<<<NN, 1024>>>(out);
    tau_kernel<<<1, 1>>>();
    thresh_kernel<<<(NN / 4) * (NN / 256), 256>>>(out);
}